// round 1
// baseline (speedup 1.0000x reference)
#include <cuda_runtime.h>
#include <cstdint>

#define NU 50000
#define NI 50000
#define NN 100000            // NU + NI
#define DD 64
#define EE 1600000
#define E2 3200000           // 2*EE directed edges
#define FULLM 0xffffffffu

// ---------------- device scratch (static, no runtime allocation) -----------
__device__ int   g_deg[NN];
__device__ float g_dinv[NN];
__device__ int   g_rowptr[NN + 1];
__device__ int   g_curpos[NN];
__device__ int   g_col[E2];
__device__ float g_w[E2];
__device__ float g_x[(size_t)NN * DD];    // ping
__device__ float g_y[(size_t)NN * DD];    // pong
__device__ float g_acc[(size_t)NN * DD];  // running sum e0 + x1 + ... + x4

// ---------------- kernels --------------------------------------------------

__global__ void k_init_deg() {
    int i = blockIdx.x * blockDim.x + threadIdx.x;
    if (i < NN) g_deg[i] = 0;
}

__global__ void k_count(const int* __restrict__ edge) {
    int e = blockIdx.x * blockDim.x + threadIdx.x;
    if (e >= EE) return;
    int u  = edge[e];
    int it = NU + edge[EE + e];
    atomicAdd(&g_deg[u], 1);
    atomicAdd(&g_deg[it], 1);
}

__global__ void k_dinv() {
    int i = blockIdx.x * blockDim.x + threadIdx.x;
    if (i >= NN) return;
    int d = g_deg[i];
    g_dinv[i] = (d > 0) ? rsqrtf((float)d) : 0.0f;
}

// single-block exclusive scan of g_deg -> g_rowptr (+ copy to g_curpos)
__global__ void k_scan() {
    __shared__ int warpsum[32];
    int lane = threadIdx.x & 31;
    int wid  = threadIdx.x >> 5;
    int carry = 0;
    for (int base = 0; base < NN; base += 1024) {
        int idx = base + (int)threadIdx.x;
        int v = (idx < NN) ? g_deg[idx] : 0;
        // inclusive warp scan
        int s = v;
        #pragma unroll
        for (int o = 1; o < 32; o <<= 1) {
            int t = __shfl_up_sync(FULLM, s, o);
            if (lane >= o) s += t;
        }
        if (lane == 31) warpsum[wid] = s;
        __syncthreads();
        if (wid == 0) {
            int ws = warpsum[lane];
            #pragma unroll
            for (int o = 1; o < 32; o <<= 1) {
                int t = __shfl_up_sync(FULLM, ws, o);
                if (lane >= o) ws += t;
            }
            warpsum[lane] = ws;
        }
        __syncthreads();
        int offset = carry + (wid > 0 ? warpsum[wid - 1] : 0);
        int excl = offset + s - v;
        if (idx < NN) { g_rowptr[idx] = excl; g_curpos[idx] = excl; }
        int total = warpsum[31];
        __syncthreads();   // protect warpsum before next chunk overwrites
        carry += total;
    }
    if (threadIdx.x == 0) g_rowptr[NN] = carry;   // == E2
}

__global__ void k_fill(const int* __restrict__ edge) {
    int e = blockIdx.x * blockDim.x + threadIdx.x;
    if (e >= EE) return;
    int u  = edge[e];
    int it = NU + edge[EE + e];
    float w = g_dinv[u] * g_dinv[it];
    int p = atomicAdd(&g_curpos[u], 1);
    g_col[p] = it;  g_w[p] = w;
    int q = atomicAdd(&g_curpos[it], 1);
    g_col[q] = u;   g_w[q] = w;
}

// x = acc = concat(user_emb, item_emb); thread per float4
__global__ void k_initx(const float* __restrict__ ue, const float* __restrict__ ie) {
    int i = blockIdx.x * blockDim.x + threadIdx.x;   // float4 index
    const int TOT = NN * DD / 4;                      // 1.6M
    if (i >= TOT) return;
    const int UQ = NU * DD / 4;
    float4 v = (i < UQ) ? ((const float4*)ue)[i] : ((const float4*)ie)[i - UQ];
    ((float4*)g_x)[i]   = v;
    ((float4*)g_acc)[i] = v;
}

// One warp per destination node: y[r][:] = sum_j w_j * x[col_j][:]; acc += y
__global__ void k_prop(int flip) {
    const float* __restrict__ x = flip ? g_y : g_x;
    float*       __restrict__ y = flip ? g_x : g_y;
    int node = (blockIdx.x * blockDim.x + threadIdx.x) >> 5;
    if (node >= NN) return;
    int lane = threadIdx.x & 31;
    int beg = g_rowptr[node];
    int end = g_rowptr[node + 1];
    float sx = 0.0f, sy = 0.0f;
    int j = beg;
    // unroll 4 neighbors for MLP
    for (; j + 4 <= end; j += 4) {
        int   c0 = g_col[j],   c1 = g_col[j+1], c2 = g_col[j+2], c3 = g_col[j+3];
        float w0 = g_w[j],     w1 = g_w[j+1],   w2 = g_w[j+2],   w3 = g_w[j+3];
        float2 v0 = *(const float2*)(x + ((size_t)c0 << 6) + (lane << 1));
        float2 v1 = *(const float2*)(x + ((size_t)c1 << 6) + (lane << 1));
        float2 v2 = *(const float2*)(x + ((size_t)c2 << 6) + (lane << 1));
        float2 v3 = *(const float2*)(x + ((size_t)c3 << 6) + (lane << 1));
        sx += w0 * v0.x; sy += w0 * v0.y;
        sx += w1 * v1.x; sy += w1 * v1.y;
        sx += w2 * v2.x; sy += w2 * v2.y;
        sx += w3 * v3.x; sy += w3 * v3.y;
    }
    for (; j < end; ++j) {
        int c = g_col[j]; float w = g_w[j];
        float2 v = *(const float2*)(x + ((size_t)c << 6) + (lane << 1));
        sx += w * v.x; sy += w * v.y;
    }
    float2* yp = (float2*)(y + ((size_t)node << 6)) + lane;
    *yp = make_float2(sx, sy);
    float2* ap = (float2*)(g_acc + ((size_t)node << 6)) + lane;
    float2 a = *ap;
    a.x += sx; a.y += sy;
    *ap = a;
}

// One warp per (user, item) pair: out = dot(acc_u, acc_i) / 25
__global__ void k_dot(const int* __restrict__ users, const int* __restrict__ items,
                      float* __restrict__ out) {
    int w = (blockIdx.x * blockDim.x + threadIdx.x) >> 5;
    if (w >= 4096) return;
    int lane = threadIdx.x & 31;
    int u  = users[w];
    int it = NU + items[w];
    float2 a = *((const float2*)(g_acc + ((size_t)u  << 6)) + lane);
    float2 b = *((const float2*)(g_acc + ((size_t)it << 6)) + lane);
    float s = a.x * b.x + a.y * b.y;
    #pragma unroll
    for (int o = 16; o; o >>= 1) s += __shfl_down_sync(FULLM, s, o);
    if (lane == 0) out[w] = s * 0.04f;   // (1/5)*(1/5) from the two means
}

// ---------------- host launcher --------------------------------------------

extern "C" void kernel_launch(void* const* d_in, const int* in_sizes, int n_in,
                              void* d_out, int out_size) {
    const float* uemb  = (const float*)d_in[0];
    const float* iemb  = (const float*)d_in[1];
    const int*   edge  = (const int*)d_in[2];
    const int*   users = (const int*)d_in[3];
    const int*   items = (const int*)d_in[4];
    float*       out   = (float*)d_out;

    const int T = 256;
    k_init_deg<<<(NN + T - 1) / T, T>>>();
    k_count   <<<(EE + T - 1) / T, T>>>(edge);
    k_dinv    <<<(NN + T - 1) / T, T>>>();
    k_scan    <<<1, 1024>>>();
    k_fill    <<<(EE + T - 1) / T, T>>>(edge);
    k_initx   <<<((NN * DD / 4) + T - 1) / T, T>>>(uemb, iemb);

    // 4 propagation layers, ping-pong between g_x and g_y
    k_prop<<<(NN * 32 + T - 1) / T, T>>>(0);
    k_prop<<<(NN * 32 + T - 1) / T, T>>>(1);
    k_prop<<<(NN * 32 + T - 1) / T, T>>>(0);
    k_prop<<<(NN * 32 + T - 1) / T, T>>>(1);

    k_dot<<<(4096 * 32 + T - 1) / T, T>>>(users, items, out);
}